// round 13
// baseline (speedup 1.0000x reference)
#include <cuda_runtime.h>
#include <cuda_bf16.h>
#include <cstdint>

#define NN 20000     // nodes
#define CI 128       // in channels
#define TT 8         // time steps
#define CO 64        // out channels
#define EE 160000    // edges
#define NB 16        // nodes per mma block (128 rows)
#define SBLK 1024    // stats blocks (7 CTAs/SM for latency hiding)

// ---------------- scratch (static device globals; no allocation) ----------------
__device__ double   g_partS[SBLK * CI];
__device__ double   g_partQ[SBLK * CI];
__device__ float    g_mean[CI];
__device__ float    g_rs[CI];                 // rsqrt(var + eps)
__device__ unsigned g_bits[NN * 32];          // spike bits: [n][t*4+k], bit l = spike(c=l+32k, t)
__device__ int      g_deg[NN];
__device__ float    g_dinv[NN];
__device__ int      g_rowptr[NN + 1];
__device__ int      g_cursor[NN];
__device__ int      g_col[EE];
__device__ float    g_wgt[EE];
__device__ float    g_y1[(size_t)NN * CO * TT];   // s @ W1^T  [n][d][t]
__device__ uint4    g_Bq[32 * 128];               // split-bf16 weights, swizzled smem layout
__device__ int      g_is64;

// ---------------- weight split helpers ----------------
__device__ __forceinline__ unsigned pack_hi(float a, float b, float& ra, float& rb) {
    __nv_bfloat16 ha = __float2bfloat16_rn(a);
    __nv_bfloat16 hb = __float2bfloat16_rn(b);
    ra = a - __bfloat162float(ha);
    rb = b - __bfloat162float(hb);
    return (unsigned)__bfloat16_as_ushort(ha) | ((unsigned)__bfloat16_as_ushort(hb) << 16);
}
__device__ __forceinline__ unsigned pack_lo(float a, float b) {
    return (unsigned)__bfloat16_as_ushort(__float2bfloat16_rn(a))
         | ((unsigned)__bfloat16_as_ushort(__float2bfloat16_rn(b)) << 16);
}

// ---------------- BN stats + init side-duties (block 0: detect; 1..79: zero deg; 80..95: wsplit) ----------------
__global__ __launch_bounds__(256) void k_stats(const float* __restrict__ x,
                                               const unsigned* __restrict__ ei,
                                               const float* __restrict__ W0,
                                               const float* __restrict__ W1) {
    int b = blockIdx.x;
    // ---- side duties (cheap, first 96 blocks only) ----
    if (b == 0) {
        __shared__ int s_nz;
        if (threadIdx.x == 0) s_nz = 0;
        __syncthreads();
        for (int j = threadIdx.x; j < 256; j += blockDim.x)
            if (ei[2 * j + 1] != 0u) atomicOr(&s_nz, 1);
        __syncthreads();
        if (threadIdx.x == 0) g_is64 = (s_nz == 0) ? 1 : 0;
    } else if (b <= 79) {
        int i = (b - 1) * 256 + threadIdx.x;
        if (i < NN) g_deg[i] = 0;
    } else if (b < 96) {
        int i = (b - 80) * 256 + threadIdx.x;   // 0..4095
        int k2g = i >> 7;
        int d   = i & 127;
        int s = k2g >> 2, tIG = k2g & 3;
        int k0 = 16 * s + 2 * tIG;
        const float* W = (d < CO) ? (W0 + (size_t)d * CI) : (W1 + (size_t)(d - CO) * CI);
        float wa = W[k0], wb = W[k0 + 1], wc = W[k0 + 8], wd = W[k0 + 9];
        float ra, rb, rc, rd;
        uint4 v;
        v.x = pack_hi(wa, wb, ra, rb);
        v.y = pack_hi(wc, wd, rc, rd);
        v.z = pack_lo(ra, rb);
        v.w = pack_lo(rc, rd);
        g_Bq[k2g * 128 + (d ^ (tIG << 1))] = v;
    }

    // ---- streaming stats: fp32 row partials, fp64 per-thread accum ----
    int tid = b * 256 + threadIdx.x;
    const int stride = SBLK * 256;   // % 128 == 0 -> channel fixed per thread
    double s = 0.0, q = 0.0;
    for (int r = tid; r < NN * CI; r += stride) {
        const float4* p = (const float4*)(x + (size_t)r * TT);
        float4 a = p[0], bb = p[1];
        float s0 = ((a.x + a.y) + (a.z + a.w)) + ((bb.x + bb.y) + (bb.z + bb.w));
        float q0 = ((a.x * a.x + a.y * a.y) + (a.z * a.z + a.w * a.w))
                 + ((bb.x * bb.x + bb.y * bb.y) + (bb.z * bb.z + bb.w * bb.w));
        s += (double)s0;
        q += (double)q0;
    }
    __shared__ double shS[256], shQ[256];
    shS[threadIdx.x] = s;
    shQ[threadIdx.x] = q;
    __syncthreads();
    if (threadIdx.x < 128) {
        int c = threadIdx.x;   // channel = tid & 127; pair partner is +128
        g_partS[b * CI + c] = shS[c] + shS[c + 128];
        g_partQ[b * CI + c] = shQ[c] + shQ[c + 128];
    }
}

__global__ void k_final() {
    int tid = threadIdx.x;          // 1024 threads: 8 per channel
    int c = tid >> 3, j = tid & 7;
    double s = 0.0, q = 0.0;
    for (int b = j; b < SBLK; b += 8) {
        s += g_partS[b * CI + c];
        q += g_partQ[b * CI + c];
    }
#pragma unroll
    for (int o = 4; o; o >>= 1) {
        s += __shfl_down_sync(0xffffffffu, s, o);
        q += __shfl_down_sync(0xffffffffu, q, o);
    }
    if (j == 0) {
        double cnt = (double)NN * (double)TT;
        double m = s / cnt;
        double var = q / cnt - m * m;
        g_mean[c] = (float)m;
        g_rs[c] = (float)(1.0 / sqrt(var + 1e-5));
    }
}

// ---------------- normalize + LIF + bit-pack (warp per node) ----------------
__global__ void k_lif(const float* __restrict__ x,
                      const float* __restrict__ gamma,
                      const float* __restrict__ beta) {
    __shared__ float sm[CI], sr[CI], sg[CI], sb[CI];
    int tid = threadIdx.x;
    if (tid < CI) { sm[tid] = g_mean[tid]; sr[tid] = g_rs[tid]; sg[tid] = gamma[tid]; sb[tid] = beta[tid]; }
    __syncthreads();
    int lane = tid & 31;
    int n = blockIdx.x * 8 + (tid >> 5);
    unsigned sp8[4];
#pragma unroll
    for (int k = 0; k < 4; k++) {
        int c = lane + 32 * k;
        const float4* p = (const float4*)(x + (size_t)n * (CI * TT) + (size_t)c * TT);
        float4 a = p[0], b = p[1];
        float m = sm[c], rs = sr[c], ga = sg[c], be = sb[c];
        float h[8];
        h[0] = __fadd_rn(__fmul_rn(__fmul_rn(ga, __fsub_rn(a.x, m)), rs), be);
        h[1] = __fadd_rn(__fmul_rn(__fmul_rn(ga, __fsub_rn(a.y, m)), rs), be);
        h[2] = __fadd_rn(__fmul_rn(__fmul_rn(ga, __fsub_rn(a.z, m)), rs), be);
        h[3] = __fadd_rn(__fmul_rn(__fmul_rn(ga, __fsub_rn(a.w, m)), rs), be);
        h[4] = __fadd_rn(__fmul_rn(__fmul_rn(ga, __fsub_rn(b.x, m)), rs), be);
        h[5] = __fadd_rn(__fmul_rn(__fmul_rn(ga, __fsub_rn(b.y, m)), rs), be);
        h[6] = __fadd_rn(__fmul_rn(__fmul_rn(ga, __fsub_rn(b.z, m)), rs), be);
        h[7] = __fadd_rn(__fmul_rn(__fmul_rn(ga, __fsub_rn(b.w, m)), rs), be);
        float mem = 0.f, spf = 0.f;
        unsigned msk = 0u;
#pragma unroll
        for (int t = 0; t < 8; t++) {
            mem = __fadd_rn(__fmul_rn(__fmul_rn(mem, 0.2f), __fsub_rn(1.f, spf)), h[t]);
            bool s = (mem > 0.5f);
            spf = s ? 1.f : 0.f;
            msk |= (s ? 1u : 0u) << t;
        }
        sp8[k] = msk;
    }
    unsigned myw = 0u;
#pragma unroll
    for (int idx = 0; idx < 32; idx++) {
        unsigned pred = (sp8[idx & 3] >> (idx >> 2)) & 1u;
        unsigned bal = __ballot_sync(0xffffffffu, pred);
        if (lane == idx) myw = bal;
    }
    g_bits[n * 32 + lane] = myw;
}

// ---------------- degree, scan, CSR build ----------------
__global__ void k_deg(const int* __restrict__ ei) {
    int e = blockIdx.x * blockDim.x + threadIdx.x;
    if (e >= EE) return;
    int is64 = g_is64;
    int d = is64 ? ei[2 * (EE + e)] : ei[EE + e];
    atomicAdd(&g_deg[d], 1);
}

__global__ void k_scan() {
    __shared__ int wsum[32];
    __shared__ int s_off;
    int tid = threadIdx.x, lane = tid & 31, w = tid >> 5;
    if (tid == 0) s_off = 0;
    __syncthreads();
    for (int base = 0; base < NN; base += 1024) {
        int i = base + tid;
        int v = (i < NN) ? g_deg[i] : 0;
        int inc = v;
#pragma unroll
        for (int d = 1; d < 32; d <<= 1) {
            int t = __shfl_up_sync(0xffffffffu, inc, d);
            if (lane >= d) inc += t;
        }
        if (lane == 31) wsum[w] = inc;
        __syncthreads();
        if (w == 0) {
            int xv = wsum[lane];
#pragma unroll
            for (int d = 1; d < 32; d <<= 1) {
                int t = __shfl_up_sync(0xffffffffu, xv, d);
                if (lane >= d) xv += t;
            }
            wsum[lane] = xv;
        }
        __syncthreads();
        int off = s_off + (w ? wsum[w - 1] : 0);
        int excl = off + inc - v;
        if (i < NN) {
            g_rowptr[i] = excl;
            g_cursor[i] = excl;
            g_dinv[i] = (v > 0) ? rsqrtf((float)v) : 0.f;
        }
        __syncthreads();
        if (tid == 0) s_off += wsum[31];
        __syncthreads();
    }
    if (threadIdx.x == 0) g_rowptr[NN] = s_off;
}

__global__ void k_csr(const int* __restrict__ ei) {
    int e = blockIdx.x * blockDim.x + threadIdx.x;
    if (e >= EE) return;
    int is64 = g_is64;
    int s = is64 ? ei[2 * e] : ei[e];
    int d = is64 ? ei[2 * (EE + e)] : ei[EE + e];
    int pos = atomicAdd(&g_cursor[d], 1);
    g_col[pos] = s;
    g_wgt[pos] = __fmul_rn(g_dinv[s], g_dinv[d]);
}

// ---------------- tensor-core GEMM: spikes (bf16 0/1) x split-bf16 weights ----------------
__device__ __forceinline__ unsigned pk(unsigned t) {
    return ((t & 1u) * 0x3F80u) | ((t & 2u) * 0x1FC00000u);
}

#define MMA16816(c, a, b0, b1)                                               \
    asm volatile(                                                            \
        "mma.sync.aligned.m16n8k16.row.col.f32.bf16.bf16.f32 "               \
        "{%0,%1,%2,%3},{%4,%5,%6,%7},{%8,%9},{%0,%1,%2,%3};"                 \
        : "+f"(c[0]), "+f"(c[1]), "+f"(c[2]), "+f"(c[3])                     \
        : "r"(a[0]), "r"(a[1]), "r"(a[2]), "r"(a[3]), "r"(b0), "r"(b1))

#define SC_STRIDE 132

__global__ __launch_bounds__(256) void k_mma(float* __restrict__ out,
                                             const float* __restrict__ bias) {
    extern __shared__ char smem[];
    uint4*    sB    = (uint4*)smem;                 // 64 KB (reused as sC)
    unsigned* sBits = (unsigned*)(sB + 32 * 128);   // 2 KB
    float*    sbias = (float*)(sBits + 128 * 4);    // 256 B (survives sC reuse)
    float*    sC    = (float*)smem;                 // 128 x SC_STRIDE floats

    int tid = threadIdx.x;
    int n0 = blockIdx.x * NB;

    for (int i = tid; i < 32 * 128; i += 256) sB[i] = g_Bq[i];
    const unsigned* gb = g_bits + (size_t)n0 * 32;
    for (int i = tid; i < NB * 32; i += 256) sBits[i] = gb[i];
    if (tid < CO) sbias[tid] = bias[tid];
    __syncthreads();

    int w = tid >> 5, lane = tid & 31;
    int g = lane >> 2, tIG = lane & 3;
    int ct = w >> 2;
    int mp = w & 3;
    int rbase = mp * 32;

    float acc[2][8][4];
#pragma unroll
    for (int m = 0; m < 2; m++)
#pragma unroll
        for (int nt = 0; nt < 8; nt++)
#pragma unroll
            for (int j = 0; j < 4; j++) acc[m][nt][j] = 0.f;

#pragma unroll
    for (int s = 0; s < 8; s++) {
        int widx = s >> 1;
        int off = (s & 1) * 16;
        int p = off + 2 * tIG;
        unsigned a[2][4];
#pragma unroll
        for (int m = 0; m < 2; m++) {
            int r0 = rbase + m * 16 + g;
            unsigned w0 = sBits[r0 * 4 + widx];
            unsigned w1 = sBits[(r0 + 8) * 4 + widx];
            a[m][0] = pk(w0 >> p);
            a[m][1] = pk(w1 >> p);
            a[m][2] = pk(w0 >> (p + 8));
            a[m][3] = pk(w1 >> (p + 8));
        }
        int krow = (s * 4 + tIG) * 128;
        int dsw = (ct * 64 + g) ^ (tIG << 1);
#pragma unroll
        for (int nt = 0; nt < 8; nt++) {
            uint4 B = sB[krow + (dsw ^ (nt * 8))];
#pragma unroll
            for (int m = 0; m < 2; m++) {
                MMA16816(acc[m][nt], a[m], B.x, B.y);   // hi
                MMA16816(acc[m][nt], a[m], B.z, B.w);   // lo
            }
        }
    }

    __syncthreads();   // sB dead; reuse as sC
#pragma unroll
    for (int m = 0; m < 2; m++)
#pragma unroll
        for (int nt = 0; nt < 8; nt++)
#pragma unroll
            for (int half = 0; half < 2; half++) {
                int r = rbase + m * 16 + g + half * 8;
                int dcomb = ct * 64 + nt * 8 + 2 * tIG;
                *(float2*)(sC + r * SC_STRIDE + dcomb) =
                    make_float2(acc[m][nt][half * 2], acc[m][nt][half * 2 + 1]);
            }
    __syncthreads();

    for (int i = tid; i < NB * 128 * 2; i += 256) {
        int nl = i >> 8;
        int rem = i & 255;
        int dcomb = rem >> 1;
        int t4 = rem & 1;
        const float* p = sC + (nl * 8 + t4 * 4) * SC_STRIDE + dcomb;
        float4 v = make_float4(p[0], p[SC_STRIDE], p[2 * SC_STRIDE], p[3 * SC_STRIDE]);
        size_t off = (size_t)(n0 + nl) * (CO * TT) + t4 * 4;
        if (dcomb < CO) {
            float bv = sbias[dcomb];
            v.x += bv; v.y += bv; v.z += bv; v.w += bv;
            *(float4*)(out + off + (size_t)dcomb * TT) = v;
        } else {
            *(float4*)(g_y1 + off + (size_t)(dcomb - CO) * TT) = v;
        }
    }
}

// ---------------- atomic-free gather, 2 nodes/block, 4-edge unroll ----------------
__global__ __launch_bounds__(256) void k_gather(float* __restrict__ out) {
    int n = blockIdx.x * 2 + (threadIdx.x >> 7);
    int t = threadIdx.x & 127;
    int beg = g_rowptr[n], end = g_rowptr[n + 1];
    float4 a0 = make_float4(0.f, 0.f, 0.f, 0.f);
    float4 a1 = make_float4(0.f, 0.f, 0.f, 0.f);
    float4 a2 = make_float4(0.f, 0.f, 0.f, 0.f);
    float4 a3 = make_float4(0.f, 0.f, 0.f, 0.f);
    int e = beg;
    for (; e + 4 <= end; e += 4) {
        int s0 = g_col[e], s1 = g_col[e + 1], s2 = g_col[e + 2], s3 = g_col[e + 3];
        float w0 = g_wgt[e], w1 = g_wgt[e + 1], w2 = g_wgt[e + 2], w3 = g_wgt[e + 3];
        float4 v0 = __ldg((const float4*)(g_y1 + (size_t)s0 * (CO * TT)) + t);
        float4 v1 = __ldg((const float4*)(g_y1 + (size_t)s1 * (CO * TT)) + t);
        float4 v2 = __ldg((const float4*)(g_y1 + (size_t)s2 * (CO * TT)) + t);
        float4 v3 = __ldg((const float4*)(g_y1 + (size_t)s3 * (CO * TT)) + t);
        a0.x = __fmaf_rn(w0, v0.x, a0.x); a0.y = __fmaf_rn(w0, v0.y, a0.y);
        a0.z = __fmaf_rn(w0, v0.z, a0.z); a0.w = __fmaf_rn(w0, v0.w, a0.w);
        a1.x = __fmaf_rn(w1, v1.x, a1.x); a1.y = __fmaf_rn(w1, v1.y, a1.y);
        a1.z = __fmaf_rn(w1, v1.z, a1.z); a1.w = __fmaf_rn(w1, v1.w, a1.w);
        a2.x = __fmaf_rn(w2, v2.x, a2.x); a2.y = __fmaf_rn(w2, v2.y, a2.y);
        a2.z = __fmaf_rn(w2, v2.z, a2.z); a2.w = __fmaf_rn(w2, v2.w, a2.w);
        a3.x = __fmaf_rn(w3, v3.x, a3.x); a3.y = __fmaf_rn(w3, v3.y, a3.y);
        a3.z = __fmaf_rn(w3, v3.z, a3.z); a3.w = __fmaf_rn(w3, v3.w, a3.w);
    }
    for (; e < end; e++) {
        int s0 = g_col[e];
        float w0 = g_wgt[e];
        float4 v0 = __ldg((const float4*)(g_y1 + (size_t)s0 * (CO * TT)) + t);
        a0.x = __fmaf_rn(w0, v0.x, a0.x); a0.y = __fmaf_rn(w0, v0.y, a0.y);
        a0.z = __fmaf_rn(w0, v0.z, a0.z); a0.w = __fmaf_rn(w0, v0.w, a0.w);
    }
    float4* o = (float4*)(out + (size_t)n * (CO * TT)) + t;
    float4 cur = *o;
    cur.x += (a0.x + a1.x) + (a2.x + a3.x);
    cur.y += (a0.y + a1.y) + (a2.y + a3.y);
    cur.z += (a0.z + a1.z) + (a2.z + a3.z);
    cur.w += (a0.w + a1.w) + (a2.w + a3.w);
    *o = cur;
}

// ---------------- launch (k_lif placed at index 3 for the ncu window) ----------------
extern "C" void kernel_launch(void* const* d_in, const int* in_sizes, int n_in,
                              void* d_out, int out_size) {
    const float* x     = (const float*)d_in[0];
    const int*   ei    = (const int*)d_in[1];
    const float* gamma = (const float*)d_in[2];
    const float* beta  = (const float*)d_in[3];
    const float* W0    = (const float*)d_in[4];
    const float* W1    = (const float*)d_in[5];
    const float* bias  = (const float*)d_in[6];
    float* out = (float*)d_out;

    const int SMEM_MMA = 32 * 128 * 16 + 128 * 4 * 4 + CO * 4;   // 67840 B
    static bool attr_done = false;
    if (!attr_done) {
        cudaFuncSetAttribute(k_mma, cudaFuncAttributeMaxDynamicSharedMemorySize, SMEM_MMA);
        attr_done = true;
    }

    k_stats <<<SBLK, 256>>>(x, (const unsigned*)ei, W0, W1);   // 0 (+init duties)
    k_final <<<1, 1024>>>();                                   // 1
    k_deg   <<<(EE + 255) / 256, 256>>>(ei);                   // 2
    k_lif   <<<NN / 8, 256>>>(x, gamma, beta);                 // 3  <-- profiled
    k_scan  <<<1, 1024>>>();                                   // 4
    k_csr   <<<(EE + 255) / 256, 256>>>(ei);                   // 5
    k_mma   <<<NN / NB, 256, SMEM_MMA>>>(out, bias);           // 6
    k_gather<<<NN / 2, 256>>>(out);                            // 7
}

// round 14
// speedup vs baseline: 1.5367x; 1.5367x over previous
#include <cuda_runtime.h>
#include <cuda_bf16.h>
#include <cstdint>

#define NN 20000     // nodes
#define CI 128       // in channels
#define TT 8         // time steps
#define CO 64        // out channels
#define EE 160000    // edges
#define NB 16        // nodes per mma block (128 rows)
#define SBLK 1024    // stats blocks (~7 CTAs/SM)

// ---------------- scratch (static device globals; no allocation) ----------------
__device__ double   g_partS[CI * SBLK];       // transposed: [c][b] for coalesced reduce
__device__ double   g_partQ[CI * SBLK];
__device__ float    g_mean[CI];
__device__ float    g_rs[CI];                 // rsqrt(var + eps)
__device__ unsigned g_bits[NN * 32];          // spike bits: [n][t*4+k], bit l = spike(c=l+32k, t)
__device__ int      g_deg[NN];
__device__ float    g_dinv[NN];
__device__ int      g_rowptr[NN + 1];
__device__ int      g_cursor[NN];
__device__ int      g_col[EE];
__device__ float    g_wgt[EE];
__device__ float    g_y1[(size_t)NN * CO * TT];   // s @ W1^T  [n][d][t]
__device__ uint4    g_Bq[32 * 128];               // split-bf16 weights, swizzled smem layout
__device__ int      g_is64;

// ---------------- weight split helpers ----------------
__device__ __forceinline__ unsigned pack_hi(float a, float b, float& ra, float& rb) {
    __nv_bfloat16 ha = __float2bfloat16_rn(a);
    __nv_bfloat16 hb = __float2bfloat16_rn(b);
    ra = a - __bfloat162float(ha);
    rb = b - __bfloat162float(hb);
    return (unsigned)__bfloat16_as_ushort(ha) | ((unsigned)__bfloat16_as_ushort(hb) << 16);
}
__device__ __forceinline__ unsigned pack_lo(float a, float b) {
    return (unsigned)__bfloat16_as_ushort(__float2bfloat16_rn(a))
         | ((unsigned)__bfloat16_as_ushort(__float2bfloat16_rn(b)) << 16);
}

// ---------------- BN stats + init side-duties (block 0: detect; 1..79: zero deg; 80..95: wsplit) ----------------
__global__ __launch_bounds__(256) void k_stats(const float* __restrict__ x,
                                               const unsigned* __restrict__ ei,
                                               const float* __restrict__ W0,
                                               const float* __restrict__ W1) {
    int b = blockIdx.x;
    if (b == 0) {
        __shared__ int s_nz;
        if (threadIdx.x == 0) s_nz = 0;
        __syncthreads();
        for (int j = threadIdx.x; j < 256; j += blockDim.x)
            if (ei[2 * j + 1] != 0u) atomicOr(&s_nz, 1);
        __syncthreads();
        if (threadIdx.x == 0) g_is64 = (s_nz == 0) ? 1 : 0;
    } else if (b <= 79) {
        int i = (b - 1) * 256 + threadIdx.x;
        if (i < NN) g_deg[i] = 0;
    } else if (b < 96) {
        int i = (b - 80) * 256 + threadIdx.x;   // 0..4095
        int k2g = i >> 7;
        int d   = i & 127;
        int s = k2g >> 2, tIG = k2g & 3;
        int k0 = 16 * s + 2 * tIG;
        const float* W = (d < CO) ? (W0 + (size_t)d * CI) : (W1 + (size_t)(d - CO) * CI);
        float wa = W[k0], wb = W[k0 + 1], wc = W[k0 + 8], wd = W[k0 + 9];
        float ra, rb, rc, rd;
        uint4 v;
        v.x = pack_hi(wa, wb, ra, rb);
        v.y = pack_hi(wc, wd, rc, rd);
        v.z = pack_lo(ra, rb);
        v.w = pack_lo(rc, rd);
        g_Bq[k2g * 128 + (d ^ (tIG << 1))] = v;
    }

    // ---- streaming stats: fp32 row partials, fp64 per-thread accum ----
    int tid = b * 256 + threadIdx.x;
    const int stride = SBLK * 256;   // % 128 == 0 -> channel fixed per thread
    double s = 0.0, q = 0.0;
    for (int r = tid; r < NN * CI; r += stride) {
        const float4* p = (const float4*)(x + (size_t)r * TT);
        float4 a = p[0], bb = p[1];
        float s0 = ((a.x + a.y) + (a.z + a.w)) + ((bb.x + bb.y) + (bb.z + bb.w));
        float q0 = ((a.x * a.x + a.y * a.y) + (a.z * a.z + a.w * a.w))
                 + ((bb.x * bb.x + bb.y * bb.y) + (bb.z * bb.z + bb.w * bb.w));
        s += (double)s0;
        q += (double)q0;
    }
    __shared__ double shS[256], shQ[256];
    shS[threadIdx.x] = s;
    shQ[threadIdx.x] = q;
    __syncthreads();
    if (threadIdx.x < 128) {
        int c = threadIdx.x;   // channel = tid & 127; pair partner is +128
        g_partS[(size_t)c * SBLK + b] = shS[c] + shS[c + 128];
        g_partQ[(size_t)c * SBLK + b] = shQ[c] + shQ[c + 128];
    }
}

// ---------------- parallel final reduce: one block per channel, coalesced ----------------
__global__ __launch_bounds__(256) void k_final() {
    int c = blockIdx.x;
    int tid = threadIdx.x;
    double s = 0.0, q = 0.0;
    const double* pS = g_partS + (size_t)c * SBLK;
    const double* pQ = g_partQ + (size_t)c * SBLK;
    for (int b = tid; b < SBLK; b += 256) { s += pS[b]; q += pQ[b]; }
    __shared__ double shS[256], shQ[256];
    shS[tid] = s; shQ[tid] = q;
    __syncthreads();
    if (tid < 128) { shS[tid] += shS[tid + 128]; shQ[tid] += shQ[tid + 128]; }
    __syncthreads();
    if (tid < 64) { shS[tid] += shS[tid + 64]; shQ[tid] += shQ[tid + 64]; }
    __syncthreads();
    if (tid < 32) {
        s = shS[tid] + shS[tid + 32];
        q = shQ[tid] + shQ[tid + 32];
#pragma unroll
        for (int o = 16; o; o >>= 1) {
            s += __shfl_down_sync(0xffffffffu, s, o);
            q += __shfl_down_sync(0xffffffffu, q, o);
        }
        if (tid == 0) {
            double cnt = (double)NN * (double)TT;
            double m = s / cnt;
            double var = q / cnt - m * m;
            g_mean[c] = (float)m;
            g_rs[c] = (float)(1.0 / sqrt(var + 1e-5));
        }
    }
}

// ---------------- normalize + LIF + bit-pack (warp per node) ----------------
__global__ void k_lif(const float* __restrict__ x,
                      const float* __restrict__ gamma,
                      const float* __restrict__ beta) {
    __shared__ float sm[CI], sr[CI], sg[CI], sb[CI];
    int tid = threadIdx.x;
    if (tid < CI) { sm[tid] = g_mean[tid]; sr[tid] = g_rs[tid]; sg[tid] = gamma[tid]; sb[tid] = beta[tid]; }
    __syncthreads();
    int lane = tid & 31;
    int n = blockIdx.x * 8 + (tid >> 5);
    unsigned sp8[4];
#pragma unroll
    for (int k = 0; k < 4; k++) {
        int c = lane + 32 * k;
        const float4* p = (const float4*)(x + (size_t)n * (CI * TT) + (size_t)c * TT);
        float4 a = p[0], b = p[1];
        float m = sm[c], rs = sr[c], ga = sg[c], be = sb[c];
        float h[8];
        h[0] = __fadd_rn(__fmul_rn(__fmul_rn(ga, __fsub_rn(a.x, m)), rs), be);
        h[1] = __fadd_rn(__fmul_rn(__fmul_rn(ga, __fsub_rn(a.y, m)), rs), be);
        h[2] = __fadd_rn(__fmul_rn(__fmul_rn(ga, __fsub_rn(a.z, m)), rs), be);
        h[3] = __fadd_rn(__fmul_rn(__fmul_rn(ga, __fsub_rn(a.w, m)), rs), be);
        h[4] = __fadd_rn(__fmul_rn(__fmul_rn(ga, __fsub_rn(b.x, m)), rs), be);
        h[5] = __fadd_rn(__fmul_rn(__fmul_rn(ga, __fsub_rn(b.y, m)), rs), be);
        h[6] = __fadd_rn(__fmul_rn(__fmul_rn(ga, __fsub_rn(b.z, m)), rs), be);
        h[7] = __fadd_rn(__fmul_rn(__fmul_rn(ga, __fsub_rn(b.w, m)), rs), be);
        float mem = 0.f, spf = 0.f;
        unsigned msk = 0u;
#pragma unroll
        for (int t = 0; t < 8; t++) {
            mem = __fadd_rn(__fmul_rn(__fmul_rn(mem, 0.2f), __fsub_rn(1.f, spf)), h[t]);
            bool s = (mem > 0.5f);
            spf = s ? 1.f : 0.f;
            msk |= (s ? 1u : 0u) << t;
        }
        sp8[k] = msk;
    }
    unsigned myw = 0u;
#pragma unroll
    for (int idx = 0; idx < 32; idx++) {
        unsigned pred = (sp8[idx & 3] >> (idx >> 2)) & 1u;
        unsigned bal = __ballot_sync(0xffffffffu, pred);
        if (lane == idx) myw = bal;
    }
    g_bits[n * 32 + lane] = myw;
}

// ---------------- degree, scan, CSR build ----------------
__global__ void k_deg(const int* __restrict__ ei) {
    int e = blockIdx.x * blockDim.x + threadIdx.x;
    if (e >= EE) return;
    int is64 = g_is64;
    int d = is64 ? ei[2 * (EE + e)] : ei[EE + e];
    atomicAdd(&g_deg[d], 1);
}

__global__ void k_scan() {
    __shared__ int wsum[32];
    __shared__ int s_off;
    int tid = threadIdx.x, lane = tid & 31, w = tid >> 5;
    if (tid == 0) s_off = 0;
    __syncthreads();
    for (int base = 0; base < NN; base += 1024) {
        int i = base + tid;
        int v = (i < NN) ? g_deg[i] : 0;
        int inc = v;
#pragma unroll
        for (int d = 1; d < 32; d <<= 1) {
            int t = __shfl_up_sync(0xffffffffu, inc, d);
            if (lane >= d) inc += t;
        }
        if (lane == 31) wsum[w] = inc;
        __syncthreads();
        if (w == 0) {
            int xv = wsum[lane];
#pragma unroll
            for (int d = 1; d < 32; d <<= 1) {
                int t = __shfl_up_sync(0xffffffffu, xv, d);
                if (lane >= d) xv += t;
            }
            wsum[lane] = xv;
        }
        __syncthreads();
        int off = s_off + (w ? wsum[w - 1] : 0);
        int excl = off + inc - v;
        if (i < NN) {
            g_rowptr[i] = excl;
            g_cursor[i] = excl;
            g_dinv[i] = (v > 0) ? rsqrtf((float)v) : 0.f;
        }
        __syncthreads();
        if (tid == 0) s_off += wsum[31];
        __syncthreads();
    }
    if (threadIdx.x == 0) g_rowptr[NN] = s_off;
}

__global__ void k_csr(const int* __restrict__ ei) {
    int e = blockIdx.x * blockDim.x + threadIdx.x;
    if (e >= EE) return;
    int is64 = g_is64;
    int s = is64 ? ei[2 * e] : ei[e];
    int d = is64 ? ei[2 * (EE + e)] : ei[EE + e];
    int pos = atomicAdd(&g_cursor[d], 1);
    g_col[pos] = s;
    g_wgt[pos] = __fmul_rn(g_dinv[s], g_dinv[d]);
}

// ---------------- tensor-core GEMM: spikes (bf16 0/1) x split-bf16 weights ----------------
__device__ __forceinline__ unsigned pk(unsigned t) {
    return ((t & 1u) * 0x3F80u) | ((t & 2u) * 0x1FC00000u);
}

#define MMA16816(c, a, b0, b1)                                               \
    asm volatile(                                                            \
        "mma.sync.aligned.m16n8k16.row.col.f32.bf16.bf16.f32 "               \
        "{%0,%1,%2,%3},{%4,%5,%6,%7},{%8,%9},{%0,%1,%2,%3};"                 \
        : "+f"(c[0]), "+f"(c[1]), "+f"(c[2]), "+f"(c[3])                     \
        : "r"(a[0]), "r"(a[1]), "r"(a[2]), "r"(a[3]), "r"(b0), "r"(b1))

#define SC_STRIDE 132

__global__ __launch_bounds__(256) void k_mma(float* __restrict__ out,
                                             const float* __restrict__ bias) {
    extern __shared__ char smem[];
    uint4*    sB    = (uint4*)smem;                 // 64 KB (reused as sC)
    unsigned* sBits = (unsigned*)(sB + 32 * 128);   // 2 KB
    float*    sbias = (float*)(sBits + 128 * 4);    // 256 B (survives sC reuse)
    float*    sC    = (float*)smem;                 // 128 x SC_STRIDE floats

    int tid = threadIdx.x;
    int n0 = blockIdx.x * NB;

    for (int i = tid; i < 32 * 128; i += 256) sB[i] = g_Bq[i];
    const unsigned* gb = g_bits + (size_t)n0 * 32;
    for (int i = tid; i < NB * 32; i += 256) sBits[i] = gb[i];
    if (tid < CO) sbias[tid] = bias[tid];
    __syncthreads();

    int w = tid >> 5, lane = tid & 31;
    int g = lane >> 2, tIG = lane & 3;
    int ct = w >> 2;
    int mp = w & 3;
    int rbase = mp * 32;

    float acc[2][8][4];
#pragma unroll
    for (int m = 0; m < 2; m++)
#pragma unroll
        for (int nt = 0; nt < 8; nt++)
#pragma unroll
            for (int j = 0; j < 4; j++) acc[m][nt][j] = 0.f;

#pragma unroll
    for (int s = 0; s < 8; s++) {
        int widx = s >> 1;
        int off = (s & 1) * 16;
        int p = off + 2 * tIG;
        unsigned a[2][4];
#pragma unroll
        for (int m = 0; m < 2; m++) {
            int r0 = rbase + m * 16 + g;
            unsigned w0 = sBits[r0 * 4 + widx];
            unsigned w1 = sBits[(r0 + 8) * 4 + widx];
            a[m][0] = pk(w0 >> p);
            a[m][1] = pk(w1 >> p);
            a[m][2] = pk(w0 >> (p + 8));
            a[m][3] = pk(w1 >> (p + 8));
        }
        int krow = (s * 4 + tIG) * 128;
        int dsw = (ct * 64 + g) ^ (tIG << 1);
#pragma unroll
        for (int nt = 0; nt < 8; nt++) {
            uint4 B = sB[krow + (dsw ^ (nt * 8))];
#pragma unroll
            for (int m = 0; m < 2; m++) {
                MMA16816(acc[m][nt], a[m], B.x, B.y);   // hi
                MMA16816(acc[m][nt], a[m], B.z, B.w);   // lo
            }
        }
    }

    __syncthreads();   // sB dead; reuse as sC
#pragma unroll
    for (int m = 0; m < 2; m++)
#pragma unroll
        for (int nt = 0; nt < 8; nt++)
#pragma unroll
            for (int half = 0; half < 2; half++) {
                int r = rbase + m * 16 + g + half * 8;
                int dcomb = ct * 64 + nt * 8 + 2 * tIG;
                *(float2*)(sC + r * SC_STRIDE + dcomb) =
                    make_float2(acc[m][nt][half * 2], acc[m][nt][half * 2 + 1]);
            }
    __syncthreads();

    for (int i = tid; i < NB * 128 * 2; i += 256) {
        int nl = i >> 8;
        int rem = i & 255;
        int dcomb = rem >> 1;
        int t4 = rem & 1;
        const float* p = sC + (nl * 8 + t4 * 4) * SC_STRIDE + dcomb;
        float4 v = make_float4(p[0], p[SC_STRIDE], p[2 * SC_STRIDE], p[3 * SC_STRIDE]);
        size_t off = (size_t)(n0 + nl) * (CO * TT) + t4 * 4;
        if (dcomb < CO) {
            float bv = sbias[dcomb];
            v.x += bv; v.y += bv; v.z += bv; v.w += bv;
            *(float4*)(out + off + (size_t)dcomb * TT) = v;
        } else {
            *(float4*)(g_y1 + off + (size_t)(dcomb - CO) * TT) = v;
        }
    }
}

// ---------------- atomic-free gather, 2 nodes/block, 2-edge unroll (R12 proven) ----------------
__global__ __launch_bounds__(256) void k_gather(float* __restrict__ out) {
    int n = blockIdx.x * 2 + (threadIdx.x >> 7);
    int t = threadIdx.x & 127;
    int beg = g_rowptr[n], end = g_rowptr[n + 1];
    float4 a0 = make_float4(0.f, 0.f, 0.f, 0.f);
    float4 a1 = make_float4(0.f, 0.f, 0.f, 0.f);
    int e = beg;
    for (; e + 2 <= end; e += 2) {
        int s0 = g_col[e], s1 = g_col[e + 1];
        float w0 = g_wgt[e], w1 = g_wgt[e + 1];
        float4 v0 = __ldg((const float4*)(g_y1 + (size_t)s0 * (CO * TT)) + t);
        float4 v1 = __ldg((const float4*)(g_y1 + (size_t)s1 * (CO * TT)) + t);
        a0.x = __fmaf_rn(w0, v0.x, a0.x); a0.y = __fmaf_rn(w0, v0.y, a0.y);
        a0.z = __fmaf_rn(w0, v0.z, a0.z); a0.w = __fmaf_rn(w0, v0.w, a0.w);
        a1.x = __fmaf_rn(w1, v1.x, a1.x); a1.y = __fmaf_rn(w1, v1.y, a1.y);
        a1.z = __fmaf_rn(w1, v1.z, a1.z); a1.w = __fmaf_rn(w1, v1.w, a1.w);
    }
    if (e < end) {
        int s0 = g_col[e];
        float w0 = g_wgt[e];
        float4 v0 = __ldg((const float4*)(g_y1 + (size_t)s0 * (CO * TT)) + t);
        a0.x = __fmaf_rn(w0, v0.x, a0.x); a0.y = __fmaf_rn(w0, v0.y, a0.y);
        a0.z = __fmaf_rn(w0, v0.z, a0.z); a0.w = __fmaf_rn(w0, v0.w, a0.w);
    }
    float4* o = (float4*)(out + (size_t)n * (CO * TT)) + t;
    float4 cur = *o;
    cur.x += a0.x + a1.x;
    cur.y += a0.y + a1.y;
    cur.z += a0.z + a1.z;
    cur.w += a0.w + a1.w;
    *o = cur;
}

// ---------------- launch (k_mma placed at index 3 for the ncu window) ----------------
extern "C" void kernel_launch(void* const* d_in, const int* in_sizes, int n_in,
                              void* d_out, int out_size) {
    const float* x     = (const float*)d_in[0];
    const int*   ei    = (const int*)d_in[1];
    const float* gamma = (const float*)d_in[2];
    const float* beta  = (const float*)d_in[3];
    const float* W0    = (const float*)d_in[4];
    const float* W1    = (const float*)d_in[5];
    const float* bias  = (const float*)d_in[6];
    float* out = (float*)d_out;

    const int SMEM_MMA = 32 * 128 * 16 + 128 * 4 * 4 + CO * 4;   // 67840 B
    static bool attr_done = false;
    if (!attr_done) {
        cudaFuncSetAttribute(k_mma, cudaFuncAttributeMaxDynamicSharedMemorySize, SMEM_MMA);
        attr_done = true;
    }

    k_stats <<<SBLK, 256>>>(x, (const unsigned*)ei, W0, W1);   // 0 (+init duties)
    k_final <<<CI, 256>>>();                                   // 1
    k_lif   <<<NN / 8, 256>>>(x, gamma, beta);                 // 2
    k_mma   <<<NN / NB, 256, SMEM_MMA>>>(out, bias);           // 3  <-- profiled
    k_deg   <<<(EE + 255) / 256, 256>>>(ei);                   // 4
    k_scan  <<<1, 1024>>>();                                   // 5
    k_csr   <<<(EE + 255) / 256, 256>>>(ei);                   // 6
    k_gather<<<NN / 2, 256>>>(out);                            // 7
}

// round 15
// speedup vs baseline: 1.5979x; 1.0399x over previous
#include <cuda_runtime.h>
#include <cuda_bf16.h>
#include <cstdint>

#define NN 20000     // nodes
#define CI 128       // in channels
#define TT 8         // time steps
#define CO 64        // out channels
#define EE 160000    // edges
#define NB 16        // nodes per mma block (128 rows)
#define SBLK 1024    // stats blocks (~7 CTAs/SM)

// ---------------- scratch (static device globals; no allocation) ----------------
__device__ double   g_partS[CI * SBLK];       // transposed: [c][b] for coalesced reduce
__device__ double   g_partQ[CI * SBLK];
__device__ float    g_mean[CI];
__device__ float    g_rs[CI];                 // rsqrt(var + eps)
__device__ unsigned g_bits[NN * 32];          // spike bits: [n][t*4+k], bit l = spike(c=l+32k, t)
__device__ int      g_deg[NN];
__device__ float    g_dinv[NN];
__device__ int      g_rowptr[NN + 1];
__device__ int      g_cursor[NN];
__device__ int      g_col[EE];
__device__ float    g_wgt[EE];
__device__ float    g_y1[(size_t)NN * CO * TT];   // s @ W1^T  [n][d][t]
__device__ uint4    g_Bq[32 * 128];               // split-bf16 weights, swizzled smem layout
__device__ int      g_is64;

// ---------------- weight split helpers ----------------
__device__ __forceinline__ unsigned pack_hi(float a, float b, float& ra, float& rb) {
    __nv_bfloat16 ha = __float2bfloat16_rn(a);
    __nv_bfloat16 hb = __float2bfloat16_rn(b);
    ra = a - __bfloat162float(ha);
    rb = b - __bfloat162float(hb);
    return (unsigned)__bfloat16_as_ushort(ha) | ((unsigned)__bfloat16_as_ushort(hb) << 16);
}
__device__ __forceinline__ unsigned pack_lo(float a, float b) {
    return (unsigned)__bfloat16_as_ushort(__float2bfloat16_rn(a))
         | ((unsigned)__bfloat16_as_ushort(__float2bfloat16_rn(b)) << 16);
}

// ---------------- BN stats + init side-duties (block 0: detect; 1..79: zero deg; 80..95: wsplit) ----------------
__global__ __launch_bounds__(256) void k_stats(const float* __restrict__ x,
                                               const unsigned* __restrict__ ei,
                                               const float* __restrict__ W0,
                                               const float* __restrict__ W1) {
    int b = blockIdx.x;
    if (b == 0) {
        __shared__ int s_nz;
        if (threadIdx.x == 0) s_nz = 0;
        __syncthreads();
        for (int j = threadIdx.x; j < 256; j += blockDim.x)
            if (ei[2 * j + 1] != 0u) atomicOr(&s_nz, 1);
        __syncthreads();
        if (threadIdx.x == 0) g_is64 = (s_nz == 0) ? 1 : 0;
    } else if (b <= 79) {
        int i = (b - 1) * 256 + threadIdx.x;
        if (i < NN) g_deg[i] = 0;
    } else if (b < 96) {
        int i = (b - 80) * 256 + threadIdx.x;   // 0..4095
        int k2g = i >> 7;
        int d   = i & 127;
        int s = k2g >> 2, tIG = k2g & 3;
        int k0 = 16 * s + 2 * tIG;
        const float* W = (d < CO) ? (W0 + (size_t)d * CI) : (W1 + (size_t)(d - CO) * CI);
        float wa = W[k0], wb = W[k0 + 1], wc = W[k0 + 8], wd = W[k0 + 9];
        float ra, rb, rc, rd;
        uint4 v;
        v.x = pack_hi(wa, wb, ra, rb);
        v.y = pack_hi(wc, wd, rc, rd);
        v.z = pack_lo(ra, rb);
        v.w = pack_lo(rc, rd);
        g_Bq[k2g * 128 + (d ^ (tIG << 1))] = v;
    }

    // ---- streaming stats: fp32 row partials, fp64 per-thread accum ----
    int tid = b * 256 + threadIdx.x;
    const int stride = SBLK * 256;   // % 128 == 0 -> channel fixed per thread
    double s = 0.0, q = 0.0;
    for (int r = tid; r < NN * CI; r += stride) {
        const float4* p = (const float4*)(x + (size_t)r * TT);
        float4 a = p[0], bb = p[1];
        float s0 = ((a.x + a.y) + (a.z + a.w)) + ((bb.x + bb.y) + (bb.z + bb.w));
        float q0 = ((a.x * a.x + a.y * a.y) + (a.z * a.z + a.w * a.w))
                 + ((bb.x * bb.x + bb.y * bb.y) + (bb.z * bb.z + bb.w * bb.w));
        s += (double)s0;
        q += (double)q0;
    }
    __shared__ double shS[256], shQ[256];
    shS[threadIdx.x] = s;
    shQ[threadIdx.x] = q;
    __syncthreads();
    if (threadIdx.x < 128) {
        int c = threadIdx.x;   // channel = tid & 127; pair partner is +128
        g_partS[(size_t)c * SBLK + b] = shS[c] + shS[c + 128];
        g_partQ[(size_t)c * SBLK + b] = shQ[c] + shQ[c + 128];
    }
}

// ---------------- parallel final reduce: one block per channel, coalesced ----------------
__global__ __launch_bounds__(256) void k_final() {
    int c = blockIdx.x;
    int tid = threadIdx.x;
    double s = 0.0, q = 0.0;
    const double* pS = g_partS + (size_t)c * SBLK;
    const double* pQ = g_partQ + (size_t)c * SBLK;
    for (int b = tid; b < SBLK; b += 256) { s += pS[b]; q += pQ[b]; }
    __shared__ double shS[256], shQ[256];
    shS[tid] = s; shQ[tid] = q;
    __syncthreads();
    if (tid < 128) { shS[tid] += shS[tid + 128]; shQ[tid] += shQ[tid + 128]; }
    __syncthreads();
    if (tid < 64) { shS[tid] += shS[tid + 64]; shQ[tid] += shQ[tid + 64]; }
    __syncthreads();
    if (tid < 32) {
        s = shS[tid] + shS[tid + 32];
        q = shQ[tid] + shQ[tid + 32];
#pragma unroll
        for (int o = 16; o; o >>= 1) {
            s += __shfl_down_sync(0xffffffffu, s, o);
            q += __shfl_down_sync(0xffffffffu, q, o);
        }
        if (tid == 0) {
            double cnt = (double)NN * (double)TT;
            double m = s / cnt;
            double var = q / cnt - m * m;
            g_mean[c] = (float)m;
            g_rs[c] = (float)(1.0 / sqrt(var + 1e-5));
        }
    }
}

// ---------------- normalize + LIF + bit-pack (warp per node) ----------------
__global__ void k_lif(const float* __restrict__ x,
                      const float* __restrict__ gamma,
                      const float* __restrict__ beta) {
    __shared__ float sm[CI], sr[CI], sg[CI], sb[CI];
    int tid = threadIdx.x;
    if (tid < CI) { sm[tid] = g_mean[tid]; sr[tid] = g_rs[tid]; sg[tid] = gamma[tid]; sb[tid] = beta[tid]; }
    __syncthreads();
    int lane = tid & 31;
    int n = blockIdx.x * 8 + (tid >> 5);
    unsigned sp8[4];
#pragma unroll
    for (int k = 0; k < 4; k++) {
        int c = lane + 32 * k;
        const float4* p = (const float4*)(x + (size_t)n * (CI * TT) + (size_t)c * TT);
        float4 a = p[0], b = p[1];
        float m = sm[c], rs = sr[c], ga = sg[c], be = sb[c];
        float h[8];
        h[0] = __fadd_rn(__fmul_rn(__fmul_rn(ga, __fsub_rn(a.x, m)), rs), be);
        h[1] = __fadd_rn(__fmul_rn(__fmul_rn(ga, __fsub_rn(a.y, m)), rs), be);
        h[2] = __fadd_rn(__fmul_rn(__fmul_rn(ga, __fsub_rn(a.z, m)), rs), be);
        h[3] = __fadd_rn(__fmul_rn(__fmul_rn(ga, __fsub_rn(a.w, m)), rs), be);
        h[4] = __fadd_rn(__fmul_rn(__fmul_rn(ga, __fsub_rn(b.x, m)), rs), be);
        h[5] = __fadd_rn(__fmul_rn(__fmul_rn(ga, __fsub_rn(b.y, m)), rs), be);
        h[6] = __fadd_rn(__fmul_rn(__fmul_rn(ga, __fsub_rn(b.z, m)), rs), be);
        h[7] = __fadd_rn(__fmul_rn(__fmul_rn(ga, __fsub_rn(b.w, m)), rs), be);
        float mem = 0.f, spf = 0.f;
        unsigned msk = 0u;
#pragma unroll
        for (int t = 0; t < 8; t++) {
            mem = __fadd_rn(__fmul_rn(__fmul_rn(mem, 0.2f), __fsub_rn(1.f, spf)), h[t]);
            bool s = (mem > 0.5f);
            spf = s ? 1.f : 0.f;
            msk |= (s ? 1u : 0u) << t;
        }
        sp8[k] = msk;
    }
    unsigned myw = 0u;
#pragma unroll
    for (int idx = 0; idx < 32; idx++) {
        unsigned pred = (sp8[idx & 3] >> (idx >> 2)) & 1u;
        unsigned bal = __ballot_sync(0xffffffffu, pred);
        if (lane == idx) myw = bal;
    }
    g_bits[n * 32 + lane] = myw;
}

// ---------------- degree, scan, CSR build ----------------
__global__ void k_deg(const int* __restrict__ ei) {
    int e = blockIdx.x * blockDim.x + threadIdx.x;
    if (e >= EE) return;
    int is64 = g_is64;
    int d = is64 ? ei[2 * (EE + e)] : ei[EE + e];
    atomicAdd(&g_deg[d], 1);
}

__global__ void k_scan() {
    __shared__ int wsum[32];
    __shared__ int s_off;
    int tid = threadIdx.x, lane = tid & 31, w = tid >> 5;
    if (tid == 0) s_off = 0;
    __syncthreads();
    for (int base = 0; base < NN; base += 1024) {
        int i = base + tid;
        int v = (i < NN) ? g_deg[i] : 0;
        int inc = v;
#pragma unroll
        for (int d = 1; d < 32; d <<= 1) {
            int t = __shfl_up_sync(0xffffffffu, inc, d);
            if (lane >= d) inc += t;
        }
        if (lane == 31) wsum[w] = inc;
        __syncthreads();
        if (w == 0) {
            int xv = wsum[lane];
#pragma unroll
            for (int d = 1; d < 32; d <<= 1) {
                int t = __shfl_up_sync(0xffffffffu, xv, d);
                if (lane >= d) xv += t;
            }
            wsum[lane] = xv;
        }
        __syncthreads();
        int off = s_off + (w ? wsum[w - 1] : 0);
        int excl = off + inc - v;
        if (i < NN) {
            g_rowptr[i] = excl;
            g_cursor[i] = excl;
            g_dinv[i] = (v > 0) ? rsqrtf((float)v) : 0.f;
        }
        __syncthreads();
        if (tid == 0) s_off += wsum[31];
        __syncthreads();
    }
    if (threadIdx.x == 0) g_rowptr[NN] = s_off;
}

__global__ void k_csr(const int* __restrict__ ei) {
    int e = blockIdx.x * blockDim.x + threadIdx.x;
    if (e >= EE) return;
    int is64 = g_is64;
    int s = is64 ? ei[2 * e] : ei[e];
    int d = is64 ? ei[2 * (EE + e)] : ei[EE + e];
    int pos = atomicAdd(&g_cursor[d], 1);
    g_col[pos] = s;
    g_wgt[pos] = __fmul_rn(g_dinv[s], g_dinv[d]);
}

// ---------------- tensor-core GEMM: spikes (bf16 0/1) x split-bf16 weights ----------------
// Split into two nt-halves so acc = 32 regs -> 2 CTAs/SM (was 1 at 141 regs).
__device__ __forceinline__ unsigned pk(unsigned t) {
    return ((t & 1u) * 0x3F80u) | ((t & 2u) * 0x1FC00000u);
}

#define MMA16816(c, a, b0, b1)                                               \
    asm volatile(                                                            \
        "mma.sync.aligned.m16n8k16.row.col.f32.bf16.bf16.f32 "               \
        "{%0,%1,%2,%3},{%4,%5,%6,%7},{%8,%9},{%0,%1,%2,%3};"                 \
        : "+f"(c[0]), "+f"(c[1]), "+f"(c[2]), "+f"(c[3])                     \
        : "r"(a[0]), "r"(a[1]), "r"(a[2]), "r"(a[3]), "r"(b0), "r"(b1))

#define SC_STRIDE 68    // padded row stride (floats) for the per-half C tile (64 cols)

// smem layout (bytes): sB 65536 | sBits 2048 | sbias 256 | sC 34816  = 102656
#define SMEM_MMA_BYTES (65536 + 2048 + 256 + 34816)

__global__ __launch_bounds__(256, 2) void k_mma(float* __restrict__ out,
                                                const float* __restrict__ bias) {
    extern __shared__ char smem[];
    uint4*    sB    = (uint4*)smem;                   // 64 KB
    unsigned* sBits = (unsigned*)(smem + 65536);      // 2 KB
    float*    sbias = (float*)(smem + 65536 + 2048);  // 256 B
    float*    sC    = (float*)(smem + 65536 + 2048 + 256);  // 128 x 68 floats

    int tid = threadIdx.x;
    int n0 = blockIdx.x * NB;

    for (int i = tid; i < 32 * 128; i += 256) sB[i] = g_Bq[i];
    const unsigned* gb = g_bits + (size_t)n0 * 32;
    for (int i = tid; i < NB * 32; i += 256) sBits[i] = gb[i];
    if (tid < CO) sbias[tid] = bias[tid];
    __syncthreads();

    int w = tid >> 5, lane = tid & 31;
    int g = lane >> 2, tIG = lane & 3;
    int ct = w >> 2;          // col half: 0 -> W0/out, 1 -> W1/y1
    int mp = w & 3;           // m-tile pair -> rows [32*mp, 32*mp+32)
    int rbase = mp * 32;
    int dsw = (ct * 64 + g) ^ (tIG << 1);

#pragma unroll
    for (int h = 0; h < 2; h++) {          // nt half: nt = 4h + nt4
        float acc[2][4][4];
#pragma unroll
        for (int m = 0; m < 2; m++)
#pragma unroll
            for (int nt4 = 0; nt4 < 4; nt4++)
#pragma unroll
                for (int j = 0; j < 4; j++) acc[m][nt4][j] = 0.f;

#pragma unroll
        for (int s = 0; s < 8; s++) {
            int widx = s >> 1;
            int p = (s & 1) * 16 + 2 * tIG;
            unsigned a[2][4];
#pragma unroll
            for (int m = 0; m < 2; m++) {
                int r0 = rbase + m * 16 + g;
                unsigned w0 = sBits[r0 * 4 + widx];
                unsigned w1 = sBits[(r0 + 8) * 4 + widx];
                a[m][0] = pk(w0 >> p);
                a[m][1] = pk(w1 >> p);
                a[m][2] = pk(w0 >> (p + 8));
                a[m][3] = pk(w1 >> (p + 8));
            }
            int krow = (s * 4 + tIG) * 128;
#pragma unroll
            for (int nt4 = 0; nt4 < 4; nt4++) {
                int nt = h * 4 + nt4;
                uint4 B = sB[krow + (dsw ^ (nt * 8))];   // nt*8 doesn't touch swizzled low bits
#pragma unroll
                for (int m = 0; m < 2; m++) {
                    MMA16816(acc[m][nt4], a[m], B.x, B.y);   // hi
                    MMA16816(acc[m][nt4], a[m], B.z, B.w);   // lo
                }
            }
        }

        // -------- per-half epilogue: transpose via sC, fully-coalesced global stores ----
        __syncthreads();   // h=1: wait until all h=0 sC reads are done (h=0: harmless)
#pragma unroll
        for (int m = 0; m < 2; m++)
#pragma unroll
            for (int nt4 = 0; nt4 < 4; nt4++)
#pragma unroll
                for (int half8 = 0; half8 < 2; half8++) {
                    int r = rbase + m * 16 + g + half8 * 8;
                    int col = ct * 32 + nt4 * 8 + 2 * tIG;
                    *(float2*)(sC + r * SC_STRIDE + col) =
                        make_float2(acc[m][nt4][half8 * 2], acc[m][nt4][half8 * 2 + 1]);
                }
        __syncthreads();

        // 2048 float4 per half: i -> (nl, col, t4); warp covers a contiguous 512B span
        for (int i = tid; i < NB * 64 * 2; i += 256) {
            int nl = i >> 7;
            int rem = i & 127;
            int col = rem >> 1;     // 0..63 within this half
            int t4 = rem & 1;
            const float* p = sC + (nl * 8 + t4 * 4) * SC_STRIDE + col;
            float4 v = make_float4(p[0], p[SC_STRIDE], p[2 * SC_STRIDE], p[3 * SC_STRIDE]);
            int d = (col & 31) + 32 * h;    // output channel within its matrix
            size_t off = (size_t)(n0 + nl) * (CO * TT) + t4 * 4;
            if (col < 32) {
                float bv = sbias[d];
                v.x += bv; v.y += bv; v.z += bv; v.w += bv;
                *(float4*)(out + off + (size_t)d * TT) = v;
            } else {
                *(float4*)(g_y1 + off + (size_t)d * TT) = v;
            }
        }
    }
}

// ---------------- atomic-free gather, 2 nodes/block, 2-edge unroll ----------------
__global__ __launch_bounds__(256) void k_gather(float* __restrict__ out) {
    int n = blockIdx.x * 2 + (threadIdx.x >> 7);
    int t = threadIdx.x & 127;
    int beg = g_rowptr[n], end = g_rowptr[n + 1];
    float4 a0 = make_float4(0.f, 0.f, 0.f, 0.f);
    float4 a1 = make_float4(0.f, 0.f, 0.f, 0.f);
    int e = beg;
    for (; e + 2 <= end; e += 2) {
        int s0 = g_col[e], s1 = g_col[e + 1];
        float w0 = g_wgt[e], w1 = g_wgt[e + 1];
        float4 v0 = __ldg((const float4*)(g_y1 + (size_t)s0 * (CO * TT)) + t);
        float4 v1 = __ldg((const float4*)(g_y1 + (size_t)s1 * (CO * TT)) + t);
        a0.x = __fmaf_rn(w0, v0.x, a0.x); a0.y = __fmaf_rn(w0, v0.y, a0.y);
        a0.z = __fmaf_rn(w0, v0.z, a0.z); a0.w = __fmaf_rn(w0, v0.w, a0.w);
        a1.x = __fmaf_rn(w1, v1.x, a1.x); a1.y = __fmaf_rn(w1, v1.y, a1.y);
        a1.z = __fmaf_rn(w1, v1.z, a1.z); a1.w = __fmaf_rn(w1, v1.w, a1.w);
    }
    if (e < end) {
        int s0 = g_col[e];
        float w0 = g_wgt[e];
        float4 v0 = __ldg((const float4*)(g_y1 + (size_t)s0 * (CO * TT)) + t);
        a0.x = __fmaf_rn(w0, v0.x, a0.x); a0.y = __fmaf_rn(w0, v0.y, a0.y);
        a0.z = __fmaf_rn(w0, v0.z, a0.z); a0.w = __fmaf_rn(w0, v0.w, a0.w);
    }
    float4* o = (float4*)(out + (size_t)n * (CO * TT)) + t;
    float4 cur = *o;
    cur.x += a0.x + a1.x;
    cur.y += a0.y + a1.y;
    cur.z += a0.z + a1.z;
    cur.w += a0.w + a1.w;
    *o = cur;
}

// ---------------- launch (k_mma at index 3 for the ncu window) ----------------
extern "C" void kernel_launch(void* const* d_in, const int* in_sizes, int n_in,
                              void* d_out, int out_size) {
    const float* x     = (const float*)d_in[0];
    const int*   ei    = (const int*)d_in[1];
    const float* gamma = (const float*)d_in[2];
    const float* beta  = (const float*)d_in[3];
    const float* W0    = (const float*)d_in[4];
    const float* W1    = (const float*)d_in[5];
    const float* bias  = (const float*)d_in[6];
    float* out = (float*)d_out;

    static bool attr_done = false;
    if (!attr_done) {
        cudaFuncSetAttribute(k_mma, cudaFuncAttributeMaxDynamicSharedMemorySize, SMEM_MMA_BYTES);
        attr_done = true;
    }

    k_stats <<<SBLK, 256>>>(x, (const unsigned*)ei, W0, W1);   // 0 (+init duties)
    k_final <<<CI, 256>>>();                                   // 1
    k_lif   <<<NN / 8, 256>>>(x, gamma, beta);                 // 2
    k_mma   <<<NN / NB, 256, SMEM_MMA_BYTES>>>(out, bias);     // 3  <-- profiled
    k_deg   <<<(EE + 255) / 256, 256>>>(ei);                   // 4
    k_scan  <<<1, 1024>>>();                                   // 5
    k_csr   <<<(EE + 255) / 256, 256>>>(ei);                   // 6
    k_gather<<<NN / 2, 256>>>(out);                            // 7
}

// round 16
// speedup vs baseline: 1.6366x; 1.0242x over previous
#include <cuda_runtime.h>
#include <cuda_bf16.h>
#include <cstdint>

#define NN 20000     // nodes
#define CI 128       // in channels
#define TT 8         // time steps
#define CO 64        // out channels
#define EE 160000    // edges
#define NB 16        // nodes per mma block (128 rows)
#define SBLK 1024    // stats blocks (~7 CTAs/SM)

// ---------------- scratch (static device globals; no allocation) ----------------
__device__ double   g_partS[CI * SBLK];       // transposed: [c][b] for coalesced reduce
__device__ double   g_partQ[CI * SBLK];
__device__ float    g_mean[CI];
__device__ float    g_rs[CI];                 // rsqrt(var + eps)
__device__ unsigned g_bits[NN * 32];          // spike bits: [n][t*4+k], bit l = spike(c=l+32k, t)
__device__ int      g_deg[NN];
__device__ float    g_dinv[NN];
__device__ int      g_rowptr[NN + 1];
__device__ int      g_cursor[NN];
__device__ int      g_col[EE];
__device__ float    g_wgt[EE];
__device__ float    g_y1[(size_t)NN * CO * TT];   // s @ W1^T  [n][d][t]
__device__ uint4    g_Bq[2 * 32 * 64];            // split-bf16 weights, [h][k2g][j'] (j' = (j&31)|((j&64)>>1))
__device__ int      g_is64;

// ---------------- weight split helpers ----------------
__device__ __forceinline__ unsigned pack_hi(float a, float b, float& ra, float& rb) {
    __nv_bfloat16 ha = __float2bfloat16_rn(a);
    __nv_bfloat16 hb = __float2bfloat16_rn(b);
    ra = a - __bfloat162float(ha);
    rb = b - __bfloat162float(hb);
    return (unsigned)__bfloat16_as_ushort(ha) | ((unsigned)__bfloat16_as_ushort(hb) << 16);
}
__device__ __forceinline__ unsigned pack_lo(float a, float b) {
    return (unsigned)__bfloat16_as_ushort(__float2bfloat16_rn(a))
         | ((unsigned)__bfloat16_as_ushort(__float2bfloat16_rn(b)) << 16);
}

// ---------------- BN stats + init side-duties (block 0: detect; 1..79: zero deg; 80..95: wsplit) ----------------
__global__ __launch_bounds__(256) void k_stats(const float* __restrict__ x,
                                               const unsigned* __restrict__ ei,
                                               const float* __restrict__ W0,
                                               const float* __restrict__ W1) {
    int b = blockIdx.x;
    if (b == 0) {
        __shared__ int s_nz;
        if (threadIdx.x == 0) s_nz = 0;
        __syncthreads();
        for (int j = threadIdx.x; j < 256; j += blockDim.x)
            if (ei[2 * j + 1] != 0u) atomicOr(&s_nz, 1);
        __syncthreads();
        if (threadIdx.x == 0) g_is64 = (s_nz == 0) ? 1 : 0;
    } else if (b <= 79) {
        int i = (b - 1) * 256 + threadIdx.x;
        if (i < NN) g_deg[i] = 0;
    } else if (b < 96) {
        int i = (b - 80) * 256 + threadIdx.x;   // 0..4095
        int k2g = i >> 7;
        int d   = i & 127;
        int s = k2g >> 2, tIG = k2g & 3;
        int k0 = 16 * s + 2 * tIG;
        const float* W = (d < CO) ? (W0 + (size_t)d * CI) : (W1 + (size_t)(d - CO) * CI);
        float wa = W[k0], wb = W[k0 + 1], wc = W[k0 + 8], wd = W[k0 + 9];
        float ra, rb, rc, rd;
        uint4 v;
        v.x = pack_hi(wa, wb, ra, rb);
        v.y = pack_hi(wc, wd, rc, rd);
        v.z = pack_lo(ra, rb);
        v.w = pack_lo(rc, rd);
        // h-split layout: j bit5 selects the nt-half that reads this column
        int j = d ^ (tIG << 1);
        int h = (j >> 5) & 1;
        int j2 = (j & 31) | ((j & 64) >> 1);
        g_Bq[h * (32 * 64) + k2g * 64 + j2] = v;
    }

    // ---- streaming stats: fp32 row partials, fp64 per-thread accum ----
    int tid = b * 256 + threadIdx.x;
    const int stride = SBLK * 256;   // % 128 == 0 -> channel fixed per thread
    double s = 0.0, q = 0.0;
    for (int r = tid; r < NN * CI; r += stride) {
        const float4* p = (const float4*)(x + (size_t)r * TT);
        float4 a = p[0], bb = p[1];
        float s0 = ((a.x + a.y) + (a.z + a.w)) + ((bb.x + bb.y) + (bb.z + bb.w));
        float q0 = ((a.x * a.x + a.y * a.y) + (a.z * a.z + a.w * a.w))
                 + ((bb.x * bb.x + bb.y * bb.y) + (bb.z * bb.z + bb.w * bb.w));
        s += (double)s0;
        q += (double)q0;
    }
    __shared__ double shS[256], shQ[256];
    shS[threadIdx.x] = s;
    shQ[threadIdx.x] = q;
    __syncthreads();
    if (threadIdx.x < 128) {
        int c = threadIdx.x;   // channel = tid & 127; pair partner is +128
        g_partS[(size_t)c * SBLK + b] = shS[c] + shS[c + 128];
        g_partQ[(size_t)c * SBLK + b] = shQ[c] + shQ[c + 128];
    }
}

// ---------------- parallel final reduce (blocks 0..127) + degree count (blocks 128..752) ----------------
__global__ __launch_bounds__(256) void k_final(const int* __restrict__ ei) {
    int blk = blockIdx.x;
    if (blk >= CI) {
        int e = (blk - CI) * 256 + threadIdx.x;
        if (e < EE) {
            int is64 = g_is64;
            int d = is64 ? ei[2 * (EE + e)] : ei[EE + e];
            atomicAdd(&g_deg[d], 1);
        }
        return;
    }
    int c = blk;
    int tid = threadIdx.x;
    double s = 0.0, q = 0.0;
    const double* pS = g_partS + (size_t)c * SBLK;
    const double* pQ = g_partQ + (size_t)c * SBLK;
    for (int b = tid; b < SBLK; b += 256) { s += pS[b]; q += pQ[b]; }
    __shared__ double shS[256], shQ[256];
    shS[tid] = s; shQ[tid] = q;
    __syncthreads();
    if (tid < 128) { shS[tid] += shS[tid + 128]; shQ[tid] += shQ[tid + 128]; }
    __syncthreads();
    if (tid < 64) { shS[tid] += shS[tid + 64]; shQ[tid] += shQ[tid + 64]; }
    __syncthreads();
    if (tid < 32) {
        s = shS[tid] + shS[tid + 32];
        q = shQ[tid] + shQ[tid + 32];
#pragma unroll
        for (int o = 16; o; o >>= 1) {
            s += __shfl_down_sync(0xffffffffu, s, o);
            q += __shfl_down_sync(0xffffffffu, q, o);
        }
        if (tid == 0) {
            double cnt = (double)NN * (double)TT;
            double m = s / cnt;
            double var = q / cnt - m * m;
            g_mean[c] = (float)m;
            g_rs[c] = (float)(1.0 / sqrt(var + 1e-5));
        }
    }
}

// ---------------- normalize + LIF + bit-pack (warp per node) ----------------
__global__ void k_lif(const float* __restrict__ x,
                      const float* __restrict__ gamma,
                      const float* __restrict__ beta) {
    __shared__ float sm[CI], sr[CI], sg[CI], sb[CI];
    int tid = threadIdx.x;
    if (tid < CI) { sm[tid] = g_mean[tid]; sr[tid] = g_rs[tid]; sg[tid] = gamma[tid]; sb[tid] = beta[tid]; }
    __syncthreads();
    int lane = tid & 31;
    int n = blockIdx.x * 8 + (tid >> 5);
    unsigned sp8[4];
#pragma unroll
    for (int k = 0; k < 4; k++) {
        int c = lane + 32 * k;
        const float4* p = (const float4*)(x + (size_t)n * (CI * TT) + (size_t)c * TT);
        float4 a = p[0], b = p[1];
        float m = sm[c], rs = sr[c], ga = sg[c], be = sb[c];
        float h[8];
        h[0] = __fadd_rn(__fmul_rn(__fmul_rn(ga, __fsub_rn(a.x, m)), rs), be);
        h[1] = __fadd_rn(__fmul_rn(__fmul_rn(ga, __fsub_rn(a.y, m)), rs), be);
        h[2] = __fadd_rn(__fmul_rn(__fmul_rn(ga, __fsub_rn(a.z, m)), rs), be);
        h[3] = __fadd_rn(__fmul_rn(__fmul_rn(ga, __fsub_rn(a.w, m)), rs), be);
        h[4] = __fadd_rn(__fmul_rn(__fmul_rn(ga, __fsub_rn(b.x, m)), rs), be);
        h[5] = __fadd_rn(__fmul_rn(__fmul_rn(ga, __fsub_rn(b.y, m)), rs), be);
        h[6] = __fadd_rn(__fmul_rn(__fmul_rn(ga, __fsub_rn(b.z, m)), rs), be);
        h[7] = __fadd_rn(__fmul_rn(__fmul_rn(ga, __fsub_rn(b.w, m)), rs), be);
        float mem = 0.f, spf = 0.f;
        unsigned msk = 0u;
#pragma unroll
        for (int t = 0; t < 8; t++) {
            mem = __fadd_rn(__fmul_rn(__fmul_rn(mem, 0.2f), __fsub_rn(1.f, spf)), h[t]);
            bool s = (mem > 0.5f);
            spf = s ? 1.f : 0.f;
            msk |= (s ? 1u : 0u) << t;
        }
        sp8[k] = msk;
    }
    unsigned myw = 0u;
#pragma unroll
    for (int idx = 0; idx < 32; idx++) {
        unsigned pred = (sp8[idx & 3] >> (idx >> 2)) & 1u;
        unsigned bal = __ballot_sync(0xffffffffu, pred);
        if (lane == idx) myw = bal;
    }
    g_bits[n * 32 + lane] = myw;
}

// ---------------- prefix scan + CSR build ----------------
__global__ void k_scan() {
    __shared__ int wsum[32];
    __shared__ int s_off;
    int tid = threadIdx.x, lane = tid & 31, w = tid >> 5;
    if (tid == 0) s_off = 0;
    __syncthreads();
    for (int base = 0; base < NN; base += 1024) {
        int i = base + tid;
        int v = (i < NN) ? g_deg[i] : 0;
        int inc = v;
#pragma unroll
        for (int d = 1; d < 32; d <<= 1) {
            int t = __shfl_up_sync(0xffffffffu, inc, d);
            if (lane >= d) inc += t;
        }
        if (lane == 31) wsum[w] = inc;
        __syncthreads();
        if (w == 0) {
            int xv = wsum[lane];
#pragma unroll
            for (int d = 1; d < 32; d <<= 1) {
                int t = __shfl_up_sync(0xffffffffu, xv, d);
                if (lane >= d) xv += t;
            }
            wsum[lane] = xv;
        }
        __syncthreads();
        int off = s_off + (w ? wsum[w - 1] : 0);
        int excl = off + inc - v;
        if (i < NN) {
            g_rowptr[i] = excl;
            g_cursor[i] = excl;
            g_dinv[i] = (v > 0) ? rsqrtf((float)v) : 0.f;
        }
        __syncthreads();
        if (tid == 0) s_off += wsum[31];
        __syncthreads();
    }
    if (threadIdx.x == 0) g_rowptr[NN] = s_off;
}

__global__ void k_csr(const int* __restrict__ ei) {
    int e = blockIdx.x * blockDim.x + threadIdx.x;
    if (e >= EE) return;
    int is64 = g_is64;
    int s = is64 ? ei[2 * e] : ei[e];
    int d = is64 ? ei[2 * (EE + e)] : ei[EE + e];
    int pos = atomicAdd(&g_cursor[d], 1);
    g_col[pos] = s;
    g_wgt[pos] = __fmul_rn(g_dinv[s], g_dinv[d]);
}

// ---------------- tensor-core GEMM: spikes (bf16 0/1) x split-bf16 weights ----------------
// Per-h sB halves (32 KB) + 32-reg acc -> 3 CTAs/SM.
__device__ __forceinline__ unsigned pk(unsigned t) {
    return ((t & 1u) * 0x3F80u) | ((t & 2u) * 0x1FC00000u);
}

#define MMA16816(c, a, b0, b1)                                               \
    asm volatile(                                                            \
        "mma.sync.aligned.m16n8k16.row.col.f32.bf16.bf16.f32 "               \
        "{%0,%1,%2,%3},{%4,%5,%6,%7},{%8,%9},{%0,%1,%2,%3};"                 \
        : "+f"(c[0]), "+f"(c[1]), "+f"(c[2]), "+f"(c[3])                     \
        : "r"(a[0]), "r"(a[1]), "r"(a[2]), "r"(a[3]), "r"(b0), "r"(b1))

#define SC_STRIDE 68    // padded row stride (floats) for the per-half C tile (64 cols)

// smem layout (bytes): sB 32768 | sBits 2048 | sbias 256 | sC 34816  = 69888
#define SMEM_MMA_BYTES (32768 + 2048 + 256 + 34816)

__global__ __launch_bounds__(256, 3) void k_mma(float* __restrict__ out,
                                                const float* __restrict__ bias) {
    extern __shared__ char smem[];
    uint4*    sB    = (uint4*)smem;                   // 32 KB (one h-half)
    unsigned* sBits = (unsigned*)(smem + 32768);      // 2 KB
    float*    sbias = (float*)(smem + 32768 + 2048);  // 256 B
    float*    sC    = (float*)(smem + 32768 + 2048 + 256);  // 128 x 68 floats

    int tid = threadIdx.x;
    int n0 = blockIdx.x * NB;

    const unsigned* gb = g_bits + (size_t)n0 * 32;
    for (int i = tid; i < NB * 32; i += 256) sBits[i] = gb[i];
    if (tid < CO) sbias[tid] = bias[tid];
    __syncthreads();

    int w = tid >> 5, lane = tid & 31;
    int g = lane >> 2, tIG = lane & 3;
    int ct = w >> 2;          // col half: 0 -> W0/out, 1 -> W1/y1
    int mp = w & 3;           // m-tile pair -> rows [32*mp, 32*mp+32)
    int rbase = mp * 32;
    int dsw5 = (g ^ (tIG << 1)) | (ct << 5);   // 6-bit read index base in the h-half layout

#pragma unroll
    for (int h = 0; h < 2; h++) {          // nt half: nt = 4h + nt4
        // load this half's B tile (32 KB); safe: all warps are past prior MMA reads
        const uint4* src = g_Bq + h * (32 * 64);
        for (int i = tid; i < 32 * 64; i += 256) sB[i] = src[i];
        __syncthreads();

        float acc[2][4][4];
#pragma unroll
        for (int m = 0; m < 2; m++)
#pragma unroll
            for (int nt4 = 0; nt4 < 4; nt4++)
#pragma unroll
                for (int j = 0; j < 4; j++) acc[m][nt4][j] = 0.f;

#pragma unroll
        for (int s = 0; s < 8; s++) {
            int widx = s >> 1;
            int p = (s & 1) * 16 + 2 * tIG;
            unsigned a[2][4];
#pragma unroll
            for (int m = 0; m < 2; m++) {
                int r0 = rbase + m * 16 + g;
                unsigned w0 = sBits[r0 * 4 + widx];
                unsigned w1 = sBits[(r0 + 8) * 4 + widx];
                a[m][0] = pk(w0 >> p);
                a[m][1] = pk(w1 >> p);
                a[m][2] = pk(w0 >> (p + 8));
                a[m][3] = pk(w1 >> (p + 8));
            }
            int krow = (s * 4 + tIG) * 64;
#pragma unroll
            for (int nt4 = 0; nt4 < 4; nt4++) {
                uint4 B = sB[krow + (dsw5 ^ (nt4 * 8))];
#pragma unroll
                for (int m = 0; m < 2; m++) {
                    MMA16816(acc[m][nt4], a[m], B.x, B.y);   // hi
                    MMA16816(acc[m][nt4], a[m], B.z, B.w);   // lo
                }
            }
        }

        // -------- per-half epilogue: transpose via sC, fully-coalesced global stores ----
        __syncthreads();   // all warps done with this sB half / prior sC reads
#pragma unroll
        for (int m = 0; m < 2; m++)
#pragma unroll
            for (int nt4 = 0; nt4 < 4; nt4++)
#pragma unroll
                for (int half8 = 0; half8 < 2; half8++) {
                    int r = rbase + m * 16 + g + half8 * 8;
                    int col = ct * 32 + nt4 * 8 + 2 * tIG;
                    *(float2*)(sC + r * SC_STRIDE + col) =
                        make_float2(acc[m][nt4][half8 * 2], acc[m][nt4][half8 * 2 + 1]);
                }
        __syncthreads();

        // 2048 float4 per half: i -> (nl, col, t4); warp covers a contiguous 512B span
        for (int i = tid; i < NB * 64 * 2; i += 256) {
            int nl = i >> 7;
            int rem = i & 127;
            int col = rem >> 1;     // 0..63 within this half
            int t4 = rem & 1;
            const float* p = sC + (nl * 8 + t4 * 4) * SC_STRIDE + col;
            float4 v = make_float4(p[0], p[SC_STRIDE], p[2 * SC_STRIDE], p[3 * SC_STRIDE]);
            int d = (col & 31) + 32 * h;    // output channel within its matrix
            size_t off = (size_t)(n0 + nl) * (CO * TT) + t4 * 4;
            if (col < 32) {
                float bv = sbias[d];
                v.x += bv; v.y += bv; v.z += bv; v.w += bv;
                *(float4*)(out + off + (size_t)d * TT) = v;
            } else {
                *(float4*)(g_y1 + off + (size_t)d * TT) = v;
            }
        }
    }
}

// ---------------- atomic-free gather, 2 nodes/block, 2-edge unroll ----------------
__global__ __launch_bounds__(256) void k_gather(float* __restrict__ out) {
    int n = blockIdx.x * 2 + (threadIdx.x >> 7);
    int t = threadIdx.x & 127;
    int beg = g_rowptr[n], end = g_rowptr[n + 1];
    float4 a0 = make_float4(0.f, 0.f, 0.f, 0.f);
    float4 a1 = make_float4(0.f, 0.f, 0.f, 0.f);
    int e = beg;
    for (; e + 2 <= end; e += 2) {
        int s0 = g_col[e], s1 = g_col[e + 1];
        float w0 = g_wgt[e], w1 = g_wgt[e + 1];
        float4 v0 = __ldg((const float4*)(g_y1 + (size_t)s0 * (CO * TT)) + t);
        float4 v1 = __ldg((const float4*)(g_y1 + (size_t)s1 * (CO * TT)) + t);
        a0.x = __fmaf_rn(w0, v0.x, a0.x); a0.y = __fmaf_rn(w0, v0.y, a0.y);
        a0.z = __fmaf_rn(w0, v0.z, a0.z); a0.w = __fmaf_rn(w0, v0.w, a0.w);
        a1.x = __fmaf_rn(w1, v1.x, a1.x); a1.y = __fmaf_rn(w1, v1.y, a1.y);
        a1.z = __fmaf_rn(w1, v1.z, a1.z); a1.w = __fmaf_rn(w1, v1.w, a1.w);
    }
    if (e < end) {
        int s0 = g_col[e];
        float w0 = g_wgt[e];
        float4 v0 = __ldg((const float4*)(g_y1 + (size_t)s0 * (CO * TT)) + t);
        a0.x = __fmaf_rn(w0, v0.x, a0.x); a0.y = __fmaf_rn(w0, v0.y, a0.y);
        a0.z = __fmaf_rn(w0, v0.z, a0.z); a0.w = __fmaf_rn(w0, v0.w, a0.w);
    }
    float4* o = (float4*)(out + (size_t)n * (CO * TT)) + t;
    float4 cur = *o;
    cur.x += a0.x + a1.x;
    cur.y += a0.y + a1.y;
    cur.z += a0.z + a1.z;
    cur.w += a0.w + a1.w;
    *o = cur;
}

// ---------------- launch (k_mma at index 3 for the ncu window) ----------------
extern "C" void kernel_launch(void* const* d_in, const int* in_sizes, int n_in,
                              void* d_out, int out_size) {
    const float* x     = (const float*)d_in[0];
    const int*   ei    = (const int*)d_in[1];
    const float* gamma = (const float*)d_in[2];
    const float* beta  = (const float*)d_in[3];
    const float* W0    = (const float*)d_in[4];
    const float* W1    = (const float*)d_in[5];
    const float* bias  = (const float*)d_in[6];
    float* out = (float*)d_out;

    static bool attr_done = false;
    if (!attr_done) {
        cudaFuncSetAttribute(k_mma, cudaFuncAttributeMaxDynamicSharedMemorySize, SMEM_MMA_BYTES);
        attr_done = true;
    }

    k_stats <<<SBLK, 256>>>(x, (const unsigned*)ei, W0, W1);   // 0 (+init duties)
    k_final <<<CI + (EE + 255) / 256, 256>>>(ei);              // 1 (+degree count)
    k_lif   <<<NN / 8, 256>>>(x, gamma, beta);                 // 2
    k_mma   <<<NN / NB, 256, SMEM_MMA_BYTES>>>(out, bias);     // 3  <-- profiled
    k_scan  <<<1, 1024>>>();                                   // 4
    k_csr   <<<(EE + 255) / 256, 256>>>(ei);                   // 5
    k_gather<<<NN / 2, 256>>>(out);                            // 6
}